// round 14
// baseline (speedup 1.0000x reference)
#include <cuda_runtime.h>
#include <cuda_bf16.h>
#include <math_constants.h>
#include <stdint.h>

#define BATCH 4
#define SEQ   2048
#define EMB   1024
#define KVH   4
#define QHN   16
#define GRP   4
#define HD    64
#define NPROJ 256
#define MROWS (BATCH*SEQ)
#define QSCALE 0.1803368801111244f   // 0.125 * log2(e)

// Pre-split storage: bf16 hi/lo planes
__device__ uint32_t g_Whi[3*512*NPROJ], g_Wlo[3*512*NPROJ];   // [mat][k2][n]
__device__ uint32_t g_Qh[BATCH*KVH*SEQ*32], g_Ql[BATCH*KVH*SEQ*32];
__device__ uint32_t g_Kh[BATCH*KVH*SEQ*32], g_Kl[BATCH*KVH*SEQ*32];
__device__ __nv_bfloat16 g_VhT[BATCH*KVH*HD*SEQ], g_VlT[BATCH*KVH*HD*SEQ]; // [bh][d][s]
__device__ float g_O[BATCH*KVH*SEQ*HD];
__device__ float2 g_rope[SEQ * 32];

// ---- helpers ---------------------------------------------------------------
__device__ __forceinline__ uint32_t pack_bf2(float x, float y) {
    __nv_bfloat162 h = __floats2bfloat162_rn(x, y);
    return *reinterpret_cast<uint32_t*>(&h);
}
__device__ __forceinline__ void split2(float x, float y, uint32_t& hi, uint32_t& lo) {
    __nv_bfloat162 h = __floats2bfloat162_rn(x, y);
    float2 hf = __bfloat1622float2(h);
    hi = *reinterpret_cast<uint32_t*>(&h);
    lo = pack_bf2(x - hf.x, y - hf.y);
}
__device__ __forceinline__ void mma16(float c[4], const uint32_t a[4], const uint32_t b[2]) {
    asm volatile("mma.sync.aligned.m16n8k16.row.col.f32.bf16.bf16.f32 "
        "{%0,%1,%2,%3}, {%4,%5,%6,%7}, {%8,%9}, {%0,%1,%2,%3};\n"
        : "+f"(c[0]), "+f"(c[1]), "+f"(c[2]), "+f"(c[3])
        : "r"(a[0]), "r"(a[1]), "r"(a[2]), "r"(a[3]), "r"(b[0]), "r"(b[1]));
}
__device__ __forceinline__ void ldsm4(uint32_t r[4], uint32_t addr) {
    asm volatile("ldmatrix.sync.aligned.m8n8.x4.shared.b16 {%0,%1,%2,%3}, [%4];"
        : "=r"(r[0]), "=r"(r[1]), "=r"(r[2]), "=r"(r[3]) : "r"(addr) : "memory");
}
__device__ __forceinline__ void cpa16(uint32_t dst, const void* src) {
    asm volatile("cp.async.cg.shared.global [%0], [%1], 16;" :: "r"(dst), "l"(src));
}

// ---------------------------------------------------------------------------
// Kernel 0a: prep W — fold Wq over groups, split all weights into hi/lo planes.
// ---------------------------------------------------------------------------
__global__ void prep_w_kernel(const float* __restrict__ Wq,
                              const float* __restrict__ Wk,
                              const float* __restrict__ Wv) {
    int i = blockIdx.x * blockDim.x + threadIdx.x;    // 3*512*256
    int mat = i >> 17;
    int rem = i & 131071;
    int k2 = rem >> 8, n = rem & 255;
    float w0, w1;
    if (mat == 0) {
        int h = n >> 6, d = n & 63;
        w0 = 0.f; w1 = 0.f;
#pragma unroll
        for (int g = 0; g < GRP; g++) {
            w0 += Wq[(size_t)(2*k2)   * (QHN*HD) + (h*GRP + g)*HD + d];
            w1 += Wq[(size_t)(2*k2+1) * (QHN*HD) + (h*GRP + g)*HD + d];
        }
    } else {
        const float* W = (mat == 1) ? Wk : Wv;
        w0 = W[(size_t)(2*k2)   * NPROJ + n];
        w1 = W[(size_t)(2*k2+1) * NPROJ + n];
    }
    split2(w0, w1, g_Whi[i], g_Wlo[i]);
}
__global__ void rope_table_kernel() {
    int i = blockIdx.x * blockDim.x + threadIdx.x;
    int s = i >> 5, d2 = i & 31;
    float freq = powf(10000.0f, -(float)(2*d2) * (1.0f/64.0f));
    float sn, cs; sincosf((float)s * freq, &sn, &cs);
    g_rope[i] = make_float2(cs, sn);
}

// ---------------------------------------------------------------------------
// Kernel 2: QKV projection (bf16x3) + RoPE + pre-split epilogue.
// Tile 64x256 (one mat per CTA). A single-buffered (reg-prefetch LDG+STS),
// B double-buffered full-width cp.async from pre-split planes.
// smem (words): A [hi 64*20 | lo 64*20] = 2560; B 2 x [hi 16*264 | lo 16*264] = 16896.
// ---------------------------------------------------------------------------
#define ALD2 20
#define BLD2 264
#define A_STG (2*64*ALD2)         // 2560
#define A_LO  (64*ALD2)           // 1280
#define B_STG (2*16*BLD2)         // 8448
#define B_LO  (16*BLD2)           // 4224
#define P_B0  A_STG               // 2560
#define PROJ_SMEM_WORDS (A_STG + 2*B_STG)   // 19456 words = 77824 B
__global__ __launch_bounds__(256, 2) void proj_kernel(const float* __restrict__ q,
                                                      const float* __restrict__ kv) {
    extern __shared__ uint32_t psm[];
    uint32_t sbase = (uint32_t)__cvta_generic_to_shared(psm);

    int mat = blockIdx.x;              // 0=Q 1=K 2=V
    int m0  = blockIdx.y * 64;

    const float* A = (mat == 0) ? q : kv;
    int matbase = mat << 17;

    int t = threadIdx.x;
    int lane = t & 31, wid = t >> 5;
    int wm = wid & 1, wn = wid >> 1;   // 2 m-tiles x 4 n-tiles
    int g = lane >> 2, tg = lane & 3;
    int l15 = lane & 15, lhi4 = (lane >> 4) << 2;

    uint32_t a_frag_off = (uint32_t)(((wm*32 + l15)*ALD2 + lhi4) * 4);

    float c[2][8][4];
#pragma unroll
    for (int mt = 0; mt < 2; mt++)
#pragma unroll
        for (int nt = 0; nt < 8; nt++)
#pragma unroll
            for (int j = 0; j < 4; j++) c[mt][nt][j] = 0.f;

    uint32_t* Ah = psm;
    uint32_t* Al = psm + A_LO;

    auto ldgA = [&](float4* av, int k0) {
#pragma unroll
        for (int i2 = 0; i2 < 2; i2++) {
            int lin = t + i2 * 256;
            av[i2] = *(const float4*)&A[(size_t)(m0 + (lin >> 3)) * EMB + k0 + (lin & 7) * 4];
        }
    };
    auto stsA = [&](const float4* av) {
#pragma unroll
        for (int i2 = 0; i2 < 2; i2++) {
            int lin = t + i2 * 256;
            int r = lin >> 3, c4 = (lin & 7) * 4;
            int k2 = c4 >> 1;
            uint32_t h0, l0, h1, l1;
            split2(av[i2].x, av[i2].y, h0, l0);
            split2(av[i2].z, av[i2].w, h1, l1);
            *(uint2*)&Ah[r*ALD2 + k2] = make_uint2(h0, h1);
            *(uint2*)&Al[r*ALD2 + k2] = make_uint2(l0, l1);
        }
    };
    auto cpaB = [&](int stage, int k0) {
        uint32_t bb = sbase + (uint32_t)((P_B0 + stage * B_STG) * 4);
        int k20 = k0 >> 1;
#pragma unroll
        for (int j = 0; j < 8; j++) {
            int qi = t + j * 256;               // 2 planes x 16 rows x 64 quads
            int pl = qi >> 10;
            int q10 = qi & 1023;
            int row = q10 >> 6, qd = (q10 & 63) * 4;
            const uint32_t* src = (pl ? g_Wlo : g_Whi) + matbase + (k20 + row) * 256 + qd;
            cpa16(bb + (uint32_t)((pl * B_LO + row * BLD2 + qd) * 4), src);
        }
    };

    float4 av[2];
    ldgA(av, 0);
    cpaB(0, 0);
    asm volatile("cp.async.commit_group;");

    for (int i = 0; i < 32; i++) {
        if (i) __syncthreads();       // A buffer readers (chunk i-1) done
        stsA(av);
        if (i + 1 < 32) {
            ldgA(av, (i + 1) * 32);
            cpaB((i + 1) & 1, (i + 1) * 32);
            asm volatile("cp.async.commit_group;");
            asm volatile("cp.async.wait_group 1;");
        } else {
            asm volatile("cp.async.wait_group 0;");
        }
        __syncthreads();

        uint32_t* Bs_hi = psm + P_B0 + (i & 1) * B_STG;
        uint32_t* Bs_lo = Bs_hi + B_LO;
        uint32_t a_hi_base = sbase + a_frag_off;
        uint32_t a_lo_base = a_hi_base + (uint32_t)(A_LO * 4);
#pragma unroll
        for (int kt = 0; kt < 2; kt++) {
            uint32_t ah[2][4], al[2][4];
#pragma unroll
            for (int mt = 0; mt < 2; mt++) {
                ldsm4(ah[mt], a_hi_base + (mt*16*ALD2 + kt*8)*4);
                ldsm4(al[mt], a_lo_base + (mt*16*ALD2 + kt*8)*4);
            }
#pragma unroll
            for (int nt = 0; nt < 8; nt++) {
                int nn = wn * 64 + nt * 8 + g;
                uint32_t bh[2], bl[2];
                bh[0] = Bs_hi[(kt*8+tg)*BLD2 + nn];   bh[1] = Bs_hi[(kt*8+tg+4)*BLD2 + nn];
                bl[0] = Bs_lo[(kt*8+tg)*BLD2 + nn];   bl[1] = Bs_lo[(kt*8+tg+4)*BLD2 + nn];
                mma16(c[0][nt], ah[0], bh);
                mma16(c[0][nt], ah[0], bl);
                mma16(c[0][nt], al[0], bh);
                mma16(c[1][nt], ah[1], bh);
                mma16(c[1][nt], ah[1], bl);
                mma16(c[1][nt], al[1], bh);
            }
        }
    }

    // epilogue: rope (Q/K), store pre-split planes (Q carries 0.125*log2e)
#pragma unroll
    for (int mt = 0; mt < 2; mt++) {
#pragma unroll
        for (int nt = 0; nt < 8; nt++) {
            int row  = m0 + wm * 32 + mt * 16 + g;
            int ncol = wn * 64 + nt * 8 + 2 * tg;
            int h = ncol >> 6, d = ncol & 63;
#pragma unroll
            for (int rr = 0; rr < 2; rr++) {
                int r2 = row + rr * 8;
                int bb = r2 >> 11, ss = r2 & 2047;
                float x1 = c[mt][nt][rr*2+0];
                float x2 = c[mt][nt][rr*2+1];
                int bh_ = bb * KVH + h;
                if (mat < 2) {
                    float2 cssn = g_rope[ss * 32 + (d >> 1)];
                    float y1 = x1*cssn.x - x2*cssn.y;
                    float y2 = x1*cssn.y + x2*cssn.x;
                    size_t idx = ((size_t)bh_ * SEQ + ss) * 32 + (d >> 1);
                    if (mat == 0) {
                        split2(y1 * QSCALE, y2 * QSCALE, g_Qh[idx], g_Ql[idx]);
                    } else {
                        split2(y1, y2, g_Kh[idx], g_Kl[idx]);
                    }
                } else {
                    size_t vb = ((size_t)bh_ * HD + d) * SEQ + ss;
                    __nv_bfloat16 h1 = __float2bfloat16_rn(x1);
                    __nv_bfloat16 h2 = __float2bfloat16_rn(x2);
                    g_VhT[vb]       = h1;
                    g_VhT[vb + SEQ] = h2;
                    g_VlT[vb]       = __float2bfloat16_rn(x1 - __bfloat162float(h1));
                    g_VlT[vb + SEQ] = __float2bfloat16_rn(x2 - __bfloat162float(h2));
                }
            }
        }
    }
}

// ---------------------------------------------------------------------------
// Kernel 3: flash attention (UNCHANGED — proven at 148 us).
// ---------------------------------------------------------------------------
#define LDW 36
#define F_QLO (128*LDW)
#define F_KV  (2*128*LDW)
#define SSTR  (4*64*LDW)
#define S_KLO (64*LDW)
#define S_VHI (2*64*LDW)
#define S_VLO (3*64*LDW)
#define FLASH_SMEM_WORDS (F_KV + 2*SSTR)   // 27648 words = 110592 B
__global__ __launch_bounds__(128, 2) void flash_kernel() {
    extern __shared__ uint32_t sm[];
    uint32_t* Qs_hi = sm;
    uint32_t* Qs_lo = sm + F_QLO;

    int t = threadIdx.x;
    int lane = t & 31, wid = t >> 5;
    int g = lane >> 2, tg = lane & 3;
    int l15 = lane & 15, lhi4 = (lane >> 4) << 2, l7 = lane & 7;
    int bh = blockIdx.y;
    int q0 = blockIdx.x * 128;
    size_t qrow0 = (size_t)bh * SEQ + q0;
    size_t krow0 = (size_t)bh * SEQ;

    uint32_t sbase = (uint32_t)__cvta_generic_to_shared(sm);
    uint32_t q_hi_base = sbase + ((wid*32 + l15)*LDW + lhi4) * 4;
    uint32_t q_lo_base = q_hi_base + F_QLO*4;
    uint32_t k_hi_base0 = sbase + (F_KV + l7*LDW + ((lane>>3)&1)*4 + (lane>>4)*8) * 4;
    uint32_t v_hi_base0 = sbase + (F_KV + S_VHI + (l7 + (lane>>4)*8)*LDW + ((lane>>3)&1)*4) * 4;

    const __nv_bfloat16* VhT = g_VhT + (size_t)bh * HD * SEQ;
    const __nv_bfloat16* VlT = g_VlT + (size_t)bh * HD * SEQ;

    int cr[4], cc[4];
#pragma unroll
    for (int i = 0; i < 4; i++) {
        int lin = t + i * 128;
        cr[i] = lin >> 3; cc[i] = (lin & 7) * 4;
    }

#pragma unroll
    for (int i = 0; i < 4; i++) {
        uint32_t d = sbase + (F_KV + cr[i]*LDW + cc[i]) * 4;
        cpa16(d,            &g_Kh[(krow0 + cr[i])*32 + cc[i]]);
        cpa16(d + S_KLO*4,  &g_Kl[(krow0 + cr[i])*32 + cc[i]]);
        cpa16(d + S_VHI*4,  VhT + (size_t)cr[i]*SEQ + cc[i]*2);
        cpa16(d + S_VLO*4,  VlT + (size_t)cr[i]*SEQ + cc[i]*2);
    }
    asm volatile("cp.async.commit_group;");
#pragma unroll
    for (int i = 0; i < 8; i++) {
        int lin = t + i * 128;
        int r = lin >> 3, c4 = (lin & 7) * 4;
        *(uint4*)&Qs_hi[r*LDW + c4] = *(const uint4*)&g_Qh[(qrow0 + r)*32 + c4];
        *(uint4*)&Qs_lo[r*LDW + c4] = *(const uint4*)&g_Ql[(qrow0 + r)*32 + c4];
    }

    float mrow[2][2], lrow[2][2];
#pragma unroll
    for (int mt = 0; mt < 2; mt++) { mrow[mt][0] = mrow[mt][1] = -CUDART_INF_F; lrow[mt][0] = lrow[mt][1] = 0.f; }
    float o[2][8][4];
#pragma unroll
    for (int mt = 0; mt < 2; mt++)
#pragma unroll
        for (int nt = 0; nt < 8; nt++)
#pragma unroll
            for (int j = 0; j < 4; j++) o[mt][nt][j] = 0.f;

    for (int it = 0; it < SEQ/64; it++) {
        if (it + 1 < SEQ/64) {
            int kt1 = (it + 1) * 64;
            uint32_t stoff = (uint32_t)(((it + 1) & 1) * SSTR) * 4;
#pragma unroll
            for (int i = 0; i < 4; i++) {
                uint32_t d = sbase + (F_KV + cr[i]*LDW + cc[i]) * 4 + stoff;
                cpa16(d,            &g_Kh[(krow0 + kt1 + cr[i])*32 + cc[i]]);
                cpa16(d + S_KLO*4,  &g_Kl[(krow0 + kt1 + cr[i])*32 + cc[i]]);
                cpa16(d + S_VHI*4,  VhT + (size_t)cr[i]*SEQ + kt1 + cc[i]*2);
                cpa16(d + S_VLO*4,  VlT + (size_t)cr[i]*SEQ + kt1 + cc[i]*2);
            }
            asm volatile("cp.async.commit_group;");
            asm volatile("cp.async.wait_group 1;");
        } else {
            asm volatile("cp.async.wait_group 0;");
        }
        __syncthreads();

        uint32_t stoff = (uint32_t)((it & 1) * SSTR) * 4;
        uint32_t k_hi_base = k_hi_base0 + stoff;
        uint32_t k_lo_base = k_hi_base + S_KLO*4;
        uint32_t v_hi_base = v_hi_base0 + stoff;
        uint32_t v_lo_base = v_hi_base + 64*LDW*4;

        float s[2][8][4];
#pragma unroll
        for (int mt = 0; mt < 2; mt++)
#pragma unroll
            for (int nt = 0; nt < 8; nt++)
#pragma unroll
                for (int j = 0; j < 4; j++) s[mt][nt][j] = 0.f;
#pragma unroll
        for (int ktp = 0; ktp < 2; ktp++) {
            uint32_t qh[2][2][4], ql[2][2][4];
#pragma unroll
            for (int mt = 0; mt < 2; mt++) {
                uint32_t moff = (uint32_t)(mt*16*LDW)*4;
                ldsm4(qh[mt][0], q_hi_base + moff + (ktp*2+0)*32);
                ldsm4(qh[mt][1], q_hi_base + moff + (ktp*2+1)*32);
                ldsm4(ql[mt][0], q_lo_base + moff + (ktp*2+0)*32);
                ldsm4(ql[mt][1], q_lo_base + moff + (ktp*2+1)*32);
            }
#pragma unroll
            for (int nt = 0; nt < 8; nt++) {
                uint32_t kh[4], klo[4];
                uint32_t off = (uint32_t)(nt*8*LDW + ktp*16)*4;
                ldsm4(kh,  k_hi_base + off);
                ldsm4(klo, k_lo_base + off);
#pragma unroll
                for (int mt = 0; mt < 2; mt++) {
                    mma16(s[mt][nt], qh[mt][0], kh);
                    mma16(s[mt][nt], qh[mt][0], klo);
                    mma16(s[mt][nt], ql[mt][0], kh);
                    mma16(s[mt][nt], qh[mt][1], kh+2);
                    mma16(s[mt][nt], qh[mt][1], klo+2);
                    mma16(s[mt][nt], ql[mt][1], kh+2);
                }
            }
        }

#pragma unroll
        for (int mt = 0; mt < 2; mt++) {
            float mx0 = -CUDART_INF_F, mx1 = -CUDART_INF_F;
#pragma unroll
            for (int nt = 0; nt < 8; nt++) {
                mx0 = fmaxf(mx0, fmaxf(s[mt][nt][0], s[mt][nt][1]));
                mx1 = fmaxf(mx1, fmaxf(s[mt][nt][2], s[mt][nt][3]));
            }
            mx0 = fmaxf(mx0, __shfl_xor_sync(0xffffffffu, mx0, 1));
            mx0 = fmaxf(mx0, __shfl_xor_sync(0xffffffffu, mx0, 2));
            mx1 = fmaxf(mx1, __shfl_xor_sync(0xffffffffu, mx1, 1));
            mx1 = fmaxf(mx1, __shfl_xor_sync(0xffffffffu, mx1, 2));
            float mn0 = fmaxf(mrow[mt][0], mx0), mn1 = fmaxf(mrow[mt][1], mx1);
            float f0 = exp2f(mrow[mt][0] - mn0), f1 = exp2f(mrow[mt][1] - mn1);
            float s0 = 0.f, s1 = 0.f;
#pragma unroll
            for (int nt = 0; nt < 8; nt++) {
                s[mt][nt][0] = exp2f(s[mt][nt][0] - mn0); s0 += s[mt][nt][0];
                s[mt][nt][1] = exp2f(s[mt][nt][1] - mn0); s0 += s[mt][nt][1];
                s[mt][nt][2] = exp2f(s[mt][nt][2] - mn1); s1 += s[mt][nt][2];
                s[mt][nt][3] = exp2f(s[mt][nt][3] - mn1); s1 += s[mt][nt][3];
            }
            s0 += __shfl_xor_sync(0xffffffffu, s0, 1);
            s0 += __shfl_xor_sync(0xffffffffu, s0, 2);
            s1 += __shfl_xor_sync(0xffffffffu, s1, 1);
            s1 += __shfl_xor_sync(0xffffffffu, s1, 2);
            lrow[mt][0] = lrow[mt][0] * f0 + s0; lrow[mt][1] = lrow[mt][1] * f1 + s1;
            mrow[mt][0] = mn0; mrow[mt][1] = mn1;
#pragma unroll
            for (int nt = 0; nt < 8; nt++) {
                o[mt][nt][0] *= f0; o[mt][nt][1] *= f0;
                o[mt][nt][2] *= f1; o[mt][nt][3] *= f1;
            }
        }

#pragma unroll
        for (int kc = 0; kc < 4; kc++) {
            uint32_t ah[2][4], al[2][4];
#pragma unroll
            for (int mt = 0; mt < 2; mt++) {
                split2(s[mt][2*kc][0],   s[mt][2*kc][1],   ah[mt][0], al[mt][0]);
                split2(s[mt][2*kc][2],   s[mt][2*kc][3],   ah[mt][1], al[mt][1]);
                split2(s[mt][2*kc+1][0], s[mt][2*kc+1][1], ah[mt][2], al[mt][2]);
                split2(s[mt][2*kc+1][2], s[mt][2*kc+1][3], ah[mt][3], al[mt][3]);
            }
#pragma unroll
            for (int n16 = 0; n16 < 4; n16++) {
                uint32_t vh4[4], vl4[4];
                uint32_t voff = (uint32_t)(n16*16*LDW + kc*8)*4;
                ldsm4(vh4, v_hi_base + voff);
                ldsm4(vl4, v_lo_base + voff);
#pragma unroll
                for (int mt = 0; mt < 2; mt++) {
                    mma16(o[mt][2*n16],   ah[mt], vh4);
                    mma16(o[mt][2*n16],   ah[mt], vl4);
                    mma16(o[mt][2*n16],   al[mt], vh4);
                    mma16(o[mt][2*n16+1], ah[mt], vh4+2);
                    mma16(o[mt][2*n16+1], ah[mt], vl4+2);
                    mma16(o[mt][2*n16+1], al[mt], vh4+2);
                }
            }
        }
        __syncthreads();
    }

    size_t obase = (size_t)bh * SEQ * HD;
#pragma unroll
    for (int mt = 0; mt < 2; mt++) {
        float inv0 = 1.f / lrow[mt][0], inv1 = 1.f / lrow[mt][1];
        int row = q0 + wid * 32 + mt * 16 + g;
#pragma unroll
        for (int nt = 0; nt < 8; nt++) {
            int d = nt * 8 + 2 * tg;
            *(float2*)&g_O[obase + (size_t)row * HD + d]       = make_float2(o[mt][nt][0]*inv0, o[mt][nt][1]*inv0);
            *(float2*)&g_O[obase + (size_t)(row + 8) * HD + d] = make_float2(o[mt][nt][2]*inv1, o[mt][nt][3]*inv1);
        }
    }
}

// ---------------------------------------------------------------------------
// Kernel 4: out = (mean_h g_O) @ Wo (bf16x3). (unchanged)
// ---------------------------------------------------------------------------
#define OALD2 36
#define OBLD2 136
__global__ __launch_bounds__(256, 2) void out_kernel(const float* __restrict__ Wo,
                                                     float* __restrict__ out) {
    extern __shared__ uint32_t osm[];
    uint32_t* As_hi = osm;
    uint32_t* As_lo = osm + 128*OALD2;
    uint32_t* Bs_hi = osm + 2*128*OALD2;
    uint32_t* Bs_lo = osm + 2*128*OALD2 + 32*OBLD2;

    int t = threadIdx.x;
    int lane = t & 31, wid = t >> 5;
    int wm = wid & 3, wn = wid >> 2;
    int g = lane >> 2, tg = lane & 3;
    int l15 = lane & 15, lhi4 = (lane >> 4) << 2;
    int m0 = blockIdx.y * 128, n0 = blockIdx.x * 128;

    uint32_t a_hi_base = (uint32_t)__cvta_generic_to_shared(osm)
                       + ((wm*32 + l15)*OALD2 + lhi4) * 4;
    uint32_t a_lo_base = a_hi_base + 128*OALD2*4;

#pragma unroll
    for (int i = 0; i < 8; i++) {
        int lin = t + i * 256;
        int r = lin >> 4, c4 = (lin & 15) * 4;
        int grow = m0 + r;
        int bb = grow >> 11, ss = grow & 2047;
        float ax = 0.f, ay = 0.f, az = 0.f, aw = 0.f;
#pragma unroll
        for (int h = 0; h < KVH; h++) {
            float4 v = *(const float4*)&g_O[(((size_t)bb * KVH + h) * SEQ + ss) * HD + c4];
            ax += v.x; ay += v.y; az += v.z; aw += v.w;
        }
        int k2 = c4 >> 1;
        split2(ax*0.25f, ay*0.25f, As_hi[r*OALD2 + k2],     As_lo[r*OALD2 + k2]);
        split2(az*0.25f, aw*0.25f, As_hi[r*OALD2 + k2 + 1], As_lo[r*OALD2 + k2 + 1]);
    }
#pragma unroll
    for (int j = 0; j < 16; j++) {
        int idx = t + j * 256;
        int k2 = idx >> 7, n = idx & 127;
        float w0 = Wo[(size_t)(2*k2) * EMB + n0 + n];
        float w1 = Wo[(size_t)(2*k2 + 1) * EMB + n0 + n];
        split2(w0, w1, Bs_hi[k2*OBLD2 + n], Bs_lo[k2*OBLD2 + n]);
    }
    __syncthreads();

    float c[2][8][4];
#pragma unroll
    for (int mt = 0; mt < 2; mt++)
#pragma unroll
        for (int nt = 0; nt < 8; nt++)
#pragma unroll
            for (int j = 0; j < 4; j++) c[mt][nt][j] = 0.f;

#pragma unroll
    for (int kt = 0; kt < 4; kt++) {
        uint32_t ah[2][4], al[2][4];
#pragma unroll
        for (int mt = 0; mt < 2; mt++) {
            ldsm4(ah[mt], a_hi_base + (mt*16*OALD2 + kt*8)*4);
            ldsm4(al[mt], a_lo_base + (mt*16*OALD2 + kt*8)*4);
        }
#pragma unroll
        for (int nt = 0; nt < 8; nt++) {
            int nn = wn * 64 + nt * 8 + g;
            uint32_t bh[2], bl[2];
            bh[0] = Bs_hi[(kt*8+tg)*OBLD2 + nn];   bh[1] = Bs_hi[(kt*8+tg+4)*OBLD2 + nn];
            bl[0] = Bs_lo[(kt*8+tg)*OBLD2 + nn];   bl[1] = Bs_lo[(kt*8+tg+4)*OBLD2 + nn];
            mma16(c[0][nt], ah[0], bh);
            mma16(c[0][nt], ah[0], bl);
            mma16(c[0][nt], al[0], bh);
            mma16(c[1][nt], ah[1], bh);
            mma16(c[1][nt], ah[1], bl);
            mma16(c[1][nt], al[1], bh);
        }
    }

#pragma unroll
    for (int mt = 0; mt < 2; mt++) {
#pragma unroll
        for (int nt = 0; nt < 8; nt++) {
            int row = m0 + wm * 32 + mt * 16 + g;
            int col = n0 + wn * 64 + nt * 8 + 2 * tg;
            *(float2*)&out[(size_t)row * EMB + col]       = make_float2(c[mt][nt][0], c[mt][nt][1]);
            *(float2*)&out[(size_t)(row + 8) * EMB + col] = make_float2(c[mt][nt][2], c[mt][nt][3]);
        }
    }
}

// ---------------------------------------------------------------------------
extern "C" void kernel_launch(void* const* d_in, const int* in_sizes, int n_in,
                              void* d_out, int out_size) {
    const float* q  = (const float*)d_in[0];
    const float* kv = (const float*)d_in[1];
    const float* Wq = (const float*)d_in[2];
    const float* Wk = (const float*)d_in[3];
    const float* Wv = (const float*)d_in[4];
    const float* Wo = (const float*)d_in[5];
    float* out = (float*)d_out;

    const int proj_smem  = PROJ_SMEM_WORDS * 4;             // 77824
    const int flash_smem = FLASH_SMEM_WORDS * 4;            // 110592
    const int out_smem   = (2*128*OALD2 + 2*32*OBLD2) * 4;  // 71680
    cudaFuncSetAttribute(proj_kernel,  cudaFuncAttributeMaxDynamicSharedMemorySize, proj_smem);
    cudaFuncSetAttribute(flash_kernel, cudaFuncAttributeMaxDynamicSharedMemorySize, flash_smem);
    cudaFuncSetAttribute(out_kernel,   cudaFuncAttributeMaxDynamicSharedMemorySize, out_smem);

    prep_w_kernel<<<(3*512*NPROJ) / 256, 256>>>(Wq, Wk, Wv);
    rope_table_kernel<<<(SEQ * 32) / 256, 256>>>();
    proj_kernel<<<dim3(3, MROWS / 64), 256, proj_smem>>>(q, kv);
    flash_kernel<<<dim3(SEQ / 128, BATCH * KVH), 128, flash_smem>>>();
    out_kernel<<<dim3(EMB / 128, MROWS / 128), 256, out_smem>>>(Wo, out);
}

// round 15
// speedup vs baseline: 1.0328x; 1.0328x over previous
#include <cuda_runtime.h>
#include <cuda_bf16.h>
#include <math_constants.h>
#include <stdint.h>

#define BATCH 4
#define SEQ   2048
#define EMB   1024
#define KVH   4
#define QHN   16
#define GRP   4
#define HD    64
#define NPROJ 256
#define MROWS (BATCH*SEQ)
#define QSCALE 0.1803368801111244f   // 0.125 * log2(e)

// Pre-split storage: bf16 hi/lo planes
__device__ uint32_t g_Whi[3*512*NPROJ], g_Wlo[3*512*NPROJ];   // [mat][k2][n]
__device__ uint32_t g_Qh[BATCH*KVH*SEQ*32], g_Ql[BATCH*KVH*SEQ*32];
__device__ uint32_t g_Kh[BATCH*KVH*SEQ*32], g_Kl[BATCH*KVH*SEQ*32];
__device__ __nv_bfloat16 g_VhT[BATCH*KVH*HD*SEQ], g_VlT[BATCH*KVH*HD*SEQ]; // [bh][d][s]
__device__ float g_O[BATCH*KVH*SEQ*HD];
__device__ float2 g_rope[SEQ * 32];

// ---- helpers ---------------------------------------------------------------
__device__ __forceinline__ uint32_t pack_bf2(float x, float y) {
    __nv_bfloat162 h = __floats2bfloat162_rn(x, y);
    return *reinterpret_cast<uint32_t*>(&h);
}
__device__ __forceinline__ void split2(float x, float y, uint32_t& hi, uint32_t& lo) {
    __nv_bfloat162 h = __floats2bfloat162_rn(x, y);
    float2 hf = __bfloat1622float2(h);
    hi = *reinterpret_cast<uint32_t*>(&h);
    lo = pack_bf2(x - hf.x, y - hf.y);
}
__device__ __forceinline__ void mma16(float c[4], const uint32_t a[4], const uint32_t b[2]) {
    asm volatile("mma.sync.aligned.m16n8k16.row.col.f32.bf16.bf16.f32 "
        "{%0,%1,%2,%3}, {%4,%5,%6,%7}, {%8,%9}, {%0,%1,%2,%3};\n"
        : "+f"(c[0]), "+f"(c[1]), "+f"(c[2]), "+f"(c[3])
        : "r"(a[0]), "r"(a[1]), "r"(a[2]), "r"(a[3]), "r"(b[0]), "r"(b[1]));
}
__device__ __forceinline__ void ldsm4(uint32_t r[4], uint32_t addr) {
    asm volatile("ldmatrix.sync.aligned.m8n8.x4.shared.b16 {%0,%1,%2,%3}, [%4];"
        : "=r"(r[0]), "=r"(r[1]), "=r"(r[2]), "=r"(r[3]) : "r"(addr) : "memory");
}
__device__ __forceinline__ void cpa16(uint32_t dst, const void* src) {
    asm volatile("cp.async.cg.shared.global [%0], [%1], 16;" :: "r"(dst), "l"(src));
}

// ---------------------------------------------------------------------------
// Kernel 0: fused prep — W fold/split planes (blocks 0..1535) + RoPE table
// (blocks 1536..1791).
// ---------------------------------------------------------------------------
__global__ void prep_kernel(const float* __restrict__ Wq,
                            const float* __restrict__ Wk,
                            const float* __restrict__ Wv) {
    int blk = blockIdx.x;
    if (blk < 1536) {
        int i = blk * 256 + threadIdx.x;      // 3*512*256
        int mat = i >> 17;
        int rem = i & 131071;
        int k2 = rem >> 8, n = rem & 255;
        float w0, w1;
        if (mat == 0) {
            int h = n >> 6, d = n & 63;
            w0 = 0.f; w1 = 0.f;
#pragma unroll
            for (int g = 0; g < GRP; g++) {
                w0 += Wq[(size_t)(2*k2)   * (QHN*HD) + (h*GRP + g)*HD + d];
                w1 += Wq[(size_t)(2*k2+1) * (QHN*HD) + (h*GRP + g)*HD + d];
            }
        } else {
            const float* W = (mat == 1) ? Wk : Wv;
            w0 = W[(size_t)(2*k2)   * NPROJ + n];
            w1 = W[(size_t)(2*k2+1) * NPROJ + n];
        }
        split2(w0, w1, g_Whi[i], g_Wlo[i]);
    } else {
        int i = (blk - 1536) * 256 + threadIdx.x;   // SEQ*32
        int s = i >> 5, d2 = i & 31;
        float freq = powf(10000.0f, -(float)(2*d2) * (1.0f/64.0f));
        float sn, cs; sincosf((float)s * freq, &sn, &cs);
        g_rope[i] = make_float2(cs, sn);
    }
}

// ---------------------------------------------------------------------------
// Kernel 2: QKV projection (bf16x3) + RoPE + pre-split epilogue.
// 3-stage ring, ONE barrier per K-32 chunk (round-13 proven config).
// ---------------------------------------------------------------------------
#define ALD2 20
#define BLD2 136
#define A_STG (2*128*ALD2)        // 5120 words per A stage
#define B_STG (2*16*BLD2)         // 4352 words per B stage
#define A_LO  (128*ALD2)          // 2560
#define B_LO  (16*BLD2)           // 2176
#define P_B0  (3*A_STG)           // 15360
#define PROJ_SMEM_WORDS (3*A_STG + 3*B_STG)   // 28416 words = 113664 B
__global__ __launch_bounds__(256, 2) void proj_kernel(const float* __restrict__ q,
                                                      const float* __restrict__ kv) {
    extern __shared__ uint32_t psm[];
    uint32_t sbase = (uint32_t)__cvta_generic_to_shared(psm);

    int bx = blockIdx.x;
    int mat   = bx >> 1;
    int ncol0 = (bx & 1) * 128;
    int m0    = blockIdx.y * 128;

    const float* A = (mat == 0) ? q : kv;
    int matbase = mat << 17;

    int t = threadIdx.x;
    int lane = t & 31, wid = t >> 5;
    int wm = wid & 3, wn = wid >> 2;
    int g = lane >> 2, tg = lane & 3;
    int l15 = lane & 15, lhi4 = (lane >> 4) << 2;

    uint32_t a_frag_off = (uint32_t)(((wm*32 + l15)*ALD2 + lhi4) * 4);

    float c[2][8][4];
#pragma unroll
    for (int mt = 0; mt < 2; mt++)
#pragma unroll
        for (int nt = 0; nt < 8; nt++)
#pragma unroll
            for (int j = 0; j < 4; j++) c[mt][nt][j] = 0.f;

    auto stsA = [&](int stage, const float4* av) {
        uint32_t* Ah = psm + stage * A_STG;
        uint32_t* Al = Ah + A_LO;
#pragma unroll
        for (int i2 = 0; i2 < 4; i2++) {
            int lin = t + i2 * 256;
            int r = lin >> 3, c4 = (lin & 7) * 4;
            int k2 = c4 >> 1;
            split2(av[i2].x, av[i2].y, Ah[r*ALD2 + k2],     Al[r*ALD2 + k2]);
            split2(av[i2].z, av[i2].w, Ah[r*ALD2 + k2 + 1], Al[r*ALD2 + k2 + 1]);
        }
    };
    auto ldgA = [&](float4* av, int k0) {
#pragma unroll
        for (int i2 = 0; i2 < 4; i2++) {
            int lin = t + i2 * 256;
            av[i2] = *(const float4*)&A[(size_t)(m0 + (lin >> 3)) * EMB + k0 + (lin & 7) * 4];
        }
    };
    auto cpaB = [&](int stage, int k0) {
        uint32_t bb = sbase + (uint32_t)((P_B0 + stage * B_STG) * 4);
#pragma unroll
        for (int j = 0; j < 2; j++) {
            int idx = t + j * 256;
            int k2r = idx >> 5, n4 = (idx & 31) * 4;
            int gidx = matbase + ((k0 >> 1) + k2r) * NPROJ + ncol0 + n4;
            cpa16(bb + (uint32_t)((k2r*BLD2 + n4) * 4),          &g_Whi[gidx]);
            cpa16(bb + (uint32_t)((B_LO + k2r*BLD2 + n4) * 4),   &g_Wlo[gidx]);
        }
    };

    float4 av[4];
    ldgA(av, 0);   stsA(0, av);  cpaB(0, 0);
    asm volatile("cp.async.commit_group;");
    ldgA(av, 32);  stsA(1, av);  cpaB(1, 32);
    asm volatile("cp.async.commit_group;");
    ldgA(av, 64);
    asm volatile("cp.async.wait_group 1;");

    int st = 0;
    for (int i = 0; i < 32; i++) {
        __syncthreads();
        uint32_t a_hi_base = sbase + (uint32_t)(st * A_STG * 4) + a_frag_off;
        uint32_t a_lo_base = a_hi_base + (uint32_t)(A_LO * 4);
        uint32_t* Bs_hi = psm + P_B0 + st * B_STG;
        uint32_t* Bs_lo = Bs_hi + B_LO;
#pragma unroll
        for (int kt = 0; kt < 2; kt++) {
            uint32_t ah[2][4], al[2][4];
#pragma unroll
            for (int mt = 0; mt < 2; mt++) {
                ldsm4(ah[mt], a_hi_base + (mt*16*ALD2 + kt*8)*4);
                ldsm4(al[mt], a_lo_base + (mt*16*ALD2 + kt*8)*4);
            }
#pragma unroll
            for (int nt = 0; nt < 8; nt++) {
                int nn = wn * 64 + nt * 8 + g;
                uint32_t bh[2], bl[2];
                bh[0] = Bs_hi[(kt*8+tg)*BLD2 + nn];   bh[1] = Bs_hi[(kt*8+tg+4)*BLD2 + nn];
                bl[0] = Bs_lo[(kt*8+tg)*BLD2 + nn];   bl[1] = Bs_lo[(kt*8+tg+4)*BLD2 + nn];
                mma16(c[0][nt], ah[0], bh);
                mma16(c[0][nt], ah[0], bl);
                mma16(c[0][nt], al[0], bh);
                mma16(c[1][nt], ah[1], bh);
                mma16(c[1][nt], ah[1], bl);
                mma16(c[1][nt], al[1], bh);
            }
        }
        int nx = i + 2;
        if (nx < 32) {
            int stw = st + 2; if (stw >= 3) stw -= 3;
            stsA(stw, av);
            if (nx + 1 < 32) ldgA(av, (nx + 1) * 32);
            cpaB(stw, nx * 32);
            asm volatile("cp.async.commit_group;");
            asm volatile("cp.async.wait_group 1;");
        } else {
            asm volatile("cp.async.wait_group 0;");
        }
        st++; if (st == 3) st = 0;
    }

    // epilogue: rope (Q/K), store pre-split planes (Q carries 0.125*log2e)
#pragma unroll
    for (int mt = 0; mt < 2; mt++) {
#pragma unroll
        for (int nt = 0; nt < 8; nt++) {
            int row  = m0 + wm * 32 + mt * 16 + g;
            int ncol = ncol0 + wn * 64 + nt * 8 + 2 * tg;
            int h = ncol >> 6, d = ncol & 63;
#pragma unroll
            for (int rr = 0; rr < 2; rr++) {
                int r2 = row + rr * 8;
                int bb = r2 >> 11, ss = r2 & 2047;
                float x1 = c[mt][nt][rr*2+0];
                float x2 = c[mt][nt][rr*2+1];
                int bh_ = bb * KVH + h;
                if (mat < 2) {
                    float2 cssn = g_rope[ss * 32 + (d >> 1)];
                    float y1 = x1*cssn.x - x2*cssn.y;
                    float y2 = x1*cssn.y + x2*cssn.x;
                    size_t idx = ((size_t)bh_ * SEQ + ss) * 32 + (d >> 1);
                    if (mat == 0) {
                        split2(y1 * QSCALE, y2 * QSCALE, g_Qh[idx], g_Ql[idx]);
                    } else {
                        split2(y1, y2, g_Kh[idx], g_Kl[idx]);
                    }
                } else {
                    size_t vb = ((size_t)bh_ * HD + d) * SEQ + ss;
                    __nv_bfloat16 h1 = __float2bfloat16_rn(x1);
                    __nv_bfloat16 h2 = __float2bfloat16_rn(x2);
                    g_VhT[vb]       = h1;
                    g_VhT[vb + SEQ] = h2;
                    g_VlT[vb]       = __float2bfloat16_rn(x1 - __bfloat162float(h1));
                    g_VlT[vb + SEQ] = __float2bfloat16_rn(x2 - __bfloat162float(h2));
                }
            }
        }
    }
}

// ---------------------------------------------------------------------------
// Kernel 3: flash attention (UNCHANGED — proven at 148 us).
// ---------------------------------------------------------------------------
#define LDW 36
#define F_QLO (128*LDW)
#define F_KV  (2*128*LDW)
#define SSTR  (4*64*LDW)
#define S_KLO (64*LDW)
#define S_VHI (2*64*LDW)
#define S_VLO (3*64*LDW)
#define FLASH_SMEM_WORDS (F_KV + 2*SSTR)   // 27648 words = 110592 B
__global__ __launch_bounds__(128, 2) void flash_kernel() {
    extern __shared__ uint32_t sm[];
    uint32_t* Qs_hi = sm;
    uint32_t* Qs_lo = sm + F_QLO;

    int t = threadIdx.x;
    int lane = t & 31, wid = t >> 5;
    int g = lane >> 2, tg = lane & 3;
    int l15 = lane & 15, lhi4 = (lane >> 4) << 2, l7 = lane & 7;
    int bh = blockIdx.y;
    int q0 = blockIdx.x * 128;
    size_t qrow0 = (size_t)bh * SEQ + q0;
    size_t krow0 = (size_t)bh * SEQ;

    uint32_t sbase = (uint32_t)__cvta_generic_to_shared(sm);
    uint32_t q_hi_base = sbase + ((wid*32 + l15)*LDW + lhi4) * 4;
    uint32_t q_lo_base = q_hi_base + F_QLO*4;
    uint32_t k_hi_base0 = sbase + (F_KV + l7*LDW + ((lane>>3)&1)*4 + (lane>>4)*8) * 4;
    uint32_t v_hi_base0 = sbase + (F_KV + S_VHI + (l7 + (lane>>4)*8)*LDW + ((lane>>3)&1)*4) * 4;

    const __nv_bfloat16* VhT = g_VhT + (size_t)bh * HD * SEQ;
    const __nv_bfloat16* VlT = g_VlT + (size_t)bh * HD * SEQ;

    int cr[4], cc[4];
#pragma unroll
    for (int i = 0; i < 4; i++) {
        int lin = t + i * 128;
        cr[i] = lin >> 3; cc[i] = (lin & 7) * 4;
    }

#pragma unroll
    for (int i = 0; i < 4; i++) {
        uint32_t d = sbase + (F_KV + cr[i]*LDW + cc[i]) * 4;
        cpa16(d,            &g_Kh[(krow0 + cr[i])*32 + cc[i]]);
        cpa16(d + S_KLO*4,  &g_Kl[(krow0 + cr[i])*32 + cc[i]]);
        cpa16(d + S_VHI*4,  VhT + (size_t)cr[i]*SEQ + cc[i]*2);
        cpa16(d + S_VLO*4,  VlT + (size_t)cr[i]*SEQ + cc[i]*2);
    }
    asm volatile("cp.async.commit_group;");
#pragma unroll
    for (int i = 0; i < 8; i++) {
        int lin = t + i * 128;
        int r = lin >> 3, c4 = (lin & 7) * 4;
        *(uint4*)&Qs_hi[r*LDW + c4] = *(const uint4*)&g_Qh[(qrow0 + r)*32 + c4];
        *(uint4*)&Qs_lo[r*LDW + c4] = *(const uint4*)&g_Ql[(qrow0 + r)*32 + c4];
    }

    float mrow[2][2], lrow[2][2];
#pragma unroll
    for (int mt = 0; mt < 2; mt++) { mrow[mt][0] = mrow[mt][1] = -CUDART_INF_F; lrow[mt][0] = lrow[mt][1] = 0.f; }
    float o[2][8][4];
#pragma unroll
    for (int mt = 0; mt < 2; mt++)
#pragma unroll
        for (int nt = 0; nt < 8; nt++)
#pragma unroll
            for (int j = 0; j < 4; j++) o[mt][nt][j] = 0.f;

    for (int it = 0; it < SEQ/64; it++) {
        if (it + 1 < SEQ/64) {
            int kt1 = (it + 1) * 64;
            uint32_t stoff = (uint32_t)(((it + 1) & 1) * SSTR) * 4;
#pragma unroll
            for (int i = 0; i < 4; i++) {
                uint32_t d = sbase + (F_KV + cr[i]*LDW + cc[i]) * 4 + stoff;
                cpa16(d,            &g_Kh[(krow0 + kt1 + cr[i])*32 + cc[i]]);
                cpa16(d + S_KLO*4,  &g_Kl[(krow0 + kt1 + cr[i])*32 + cc[i]]);
                cpa16(d + S_VHI*4,  VhT + (size_t)cr[i]*SEQ + kt1 + cc[i]*2);
                cpa16(d + S_VLO*4,  VlT + (size_t)cr[i]*SEQ + kt1 + cc[i]*2);
            }
            asm volatile("cp.async.commit_group;");
            asm volatile("cp.async.wait_group 1;");
        } else {
            asm volatile("cp.async.wait_group 0;");
        }
        __syncthreads();

        uint32_t stoff = (uint32_t)((it & 1) * SSTR) * 4;
        uint32_t k_hi_base = k_hi_base0 + stoff;
        uint32_t k_lo_base = k_hi_base + S_KLO*4;
        uint32_t v_hi_base = v_hi_base0 + stoff;
        uint32_t v_lo_base = v_hi_base + 64*LDW*4;

        float s[2][8][4];
#pragma unroll
        for (int mt = 0; mt < 2; mt++)
#pragma unroll
            for (int nt = 0; nt < 8; nt++)
#pragma unroll
                for (int j = 0; j < 4; j++) s[mt][nt][j] = 0.f;
#pragma unroll
        for (int ktp = 0; ktp < 2; ktp++) {
            uint32_t qh[2][2][4], ql[2][2][4];
#pragma unroll
            for (int mt = 0; mt < 2; mt++) {
                uint32_t moff = (uint32_t)(mt*16*LDW)*4;
                ldsm4(qh[mt][0], q_hi_base + moff + (ktp*2+0)*32);
                ldsm4(qh[mt][1], q_hi_base + moff + (ktp*2+1)*32);
                ldsm4(ql[mt][0], q_lo_base + moff + (ktp*2+0)*32);
                ldsm4(ql[mt][1], q_lo_base + moff + (ktp*2+1)*32);
            }
#pragma unroll
            for (int nt = 0; nt < 8; nt++) {
                uint32_t kh[4], klo[4];
                uint32_t off = (uint32_t)(nt*8*LDW + ktp*16)*4;
                ldsm4(kh,  k_hi_base + off);
                ldsm4(klo, k_lo_base + off);
#pragma unroll
                for (int mt = 0; mt < 2; mt++) {
                    mma16(s[mt][nt], qh[mt][0], kh);
                    mma16(s[mt][nt], qh[mt][0], klo);
                    mma16(s[mt][nt], ql[mt][0], kh);
                    mma16(s[mt][nt], qh[mt][1], kh+2);
                    mma16(s[mt][nt], qh[mt][1], klo+2);
                    mma16(s[mt][nt], ql[mt][1], kh+2);
                }
            }
        }

#pragma unroll
        for (int mt = 0; mt < 2; mt++) {
            float mx0 = -CUDART_INF_F, mx1 = -CUDART_INF_F;
#pragma unroll
            for (int nt = 0; nt < 8; nt++) {
                mx0 = fmaxf(mx0, fmaxf(s[mt][nt][0], s[mt][nt][1]));
                mx1 = fmaxf(mx1, fmaxf(s[mt][nt][2], s[mt][nt][3]));
            }
            mx0 = fmaxf(mx0, __shfl_xor_sync(0xffffffffu, mx0, 1));
            mx0 = fmaxf(mx0, __shfl_xor_sync(0xffffffffu, mx0, 2));
            mx1 = fmaxf(mx1, __shfl_xor_sync(0xffffffffu, mx1, 1));
            mx1 = fmaxf(mx1, __shfl_xor_sync(0xffffffffu, mx1, 2));
            float mn0 = fmaxf(mrow[mt][0], mx0), mn1 = fmaxf(mrow[mt][1], mx1);
            float f0 = exp2f(mrow[mt][0] - mn0), f1 = exp2f(mrow[mt][1] - mn1);
            float s0 = 0.f, s1 = 0.f;
#pragma unroll
            for (int nt = 0; nt < 8; nt++) {
                s[mt][nt][0] = exp2f(s[mt][nt][0] - mn0); s0 += s[mt][nt][0];
                s[mt][nt][1] = exp2f(s[mt][nt][1] - mn0); s0 += s[mt][nt][1];
                s[mt][nt][2] = exp2f(s[mt][nt][2] - mn1); s1 += s[mt][nt][2];
                s[mt][nt][3] = exp2f(s[mt][nt][3] - mn1); s1 += s[mt][nt][3];
            }
            s0 += __shfl_xor_sync(0xffffffffu, s0, 1);
            s0 += __shfl_xor_sync(0xffffffffu, s0, 2);
            s1 += __shfl_xor_sync(0xffffffffu, s1, 1);
            s1 += __shfl_xor_sync(0xffffffffu, s1, 2);
            lrow[mt][0] = lrow[mt][0] * f0 + s0; lrow[mt][1] = lrow[mt][1] * f1 + s1;
            mrow[mt][0] = mn0; mrow[mt][1] = mn1;
#pragma unroll
            for (int nt = 0; nt < 8; nt++) {
                o[mt][nt][0] *= f0; o[mt][nt][1] *= f0;
                o[mt][nt][2] *= f1; o[mt][nt][3] *= f1;
            }
        }

#pragma unroll
        for (int kc = 0; kc < 4; kc++) {
            uint32_t ah[2][4], al[2][4];
#pragma unroll
            for (int mt = 0; mt < 2; mt++) {
                split2(s[mt][2*kc][0],   s[mt][2*kc][1],   ah[mt][0], al[mt][0]);
                split2(s[mt][2*kc][2],   s[mt][2*kc][3],   ah[mt][1], al[mt][1]);
                split2(s[mt][2*kc+1][0], s[mt][2*kc+1][1], ah[mt][2], al[mt][2]);
                split2(s[mt][2*kc+1][2], s[mt][2*kc+1][3], ah[mt][3], al[mt][3]);
            }
#pragma unroll
            for (int n16 = 0; n16 < 4; n16++) {
                uint32_t vh4[4], vl4[4];
                uint32_t voff = (uint32_t)(n16*16*LDW + kc*8)*4;
                ldsm4(vh4, v_hi_base + voff);
                ldsm4(vl4, v_lo_base + voff);
#pragma unroll
                for (int mt = 0; mt < 2; mt++) {
                    mma16(o[mt][2*n16],   ah[mt], vh4);
                    mma16(o[mt][2*n16],   ah[mt], vl4);
                    mma16(o[mt][2*n16],   al[mt], vh4);
                    mma16(o[mt][2*n16+1], ah[mt], vh4+2);
                    mma16(o[mt][2*n16+1], ah[mt], vl4+2);
                    mma16(o[mt][2*n16+1], al[mt], vh4+2);
                }
            }
        }
        __syncthreads();
    }

    size_t obase = (size_t)bh * SEQ * HD;
#pragma unroll
    for (int mt = 0; mt < 2; mt++) {
        float inv0 = 1.f / lrow[mt][0], inv1 = 1.f / lrow[mt][1];
        int row = q0 + wid * 32 + mt * 16 + g;
#pragma unroll
        for (int nt = 0; nt < 8; nt++) {
            int d = nt * 8 + 2 * tg;
            *(float2*)&g_O[obase + (size_t)row * HD + d]       = make_float2(o[mt][nt][0]*inv0, o[mt][nt][1]*inv0);
            *(float2*)&g_O[obase + (size_t)(row + 8) * HD + d] = make_float2(o[mt][nt][2]*inv1, o[mt][nt][3]*inv1);
        }
    }
}

// ---------------------------------------------------------------------------
// Kernel 4: out = (mean_h g_O) @ Wo (bf16x3). (unchanged)
// ---------------------------------------------------------------------------
#define OALD2 36
#define OBLD2 136
__global__ __launch_bounds__(256, 2) void out_kernel(const float* __restrict__ Wo,
                                                     float* __restrict__ out) {
    extern __shared__ uint32_t osm[];
    uint32_t* As_hi = osm;
    uint32_t* As_lo = osm + 128*OALD2;
    uint32_t* Bs_hi = osm + 2*128*OALD2;
    uint32_t* Bs_lo = osm + 2*128*OALD2 + 32*OBLD2;

    int t = threadIdx.x;
    int lane = t & 31, wid = t >> 5;
    int wm = wid & 3, wn = wid >> 2;
    int g = lane >> 2, tg = lane & 3;
    int l15 = lane & 15, lhi4 = (lane >> 4) << 2;
    int m0 = blockIdx.y * 128, n0 = blockIdx.x * 128;

    uint32_t a_hi_base = (uint32_t)__cvta_generic_to_shared(osm)
                       + ((wm*32 + l15)*OALD2 + lhi4) * 4;
    uint32_t a_lo_base = a_hi_base + 128*OALD2*4;

#pragma unroll
    for (int i = 0; i < 8; i++) {
        int lin = t + i * 256;
        int r = lin >> 4, c4 = (lin & 15) * 4;
        int grow = m0 + r;
        int bb = grow >> 11, ss = grow & 2047;
        float ax = 0.f, ay = 0.f, az = 0.f, aw = 0.f;
#pragma unroll
        for (int h = 0; h < KVH; h++) {
            float4 v = *(const float4*)&g_O[(((size_t)bb * KVH + h) * SEQ + ss) * HD + c4];
            ax += v.x; ay += v.y; az += v.z; aw += v.w;
        }
        int k2 = c4 >> 1;
        split2(ax*0.25f, ay*0.25f, As_hi[r*OALD2 + k2],     As_lo[r*OALD2 + k2]);
        split2(az*0.25f, aw*0.25f, As_hi[r*OALD2 + k2 + 1], As_lo[r*OALD2 + k2 + 1]);
    }
#pragma unroll
    for (int j = 0; j < 16; j++) {
        int idx = t + j * 256;
        int k2 = idx >> 7, n = idx & 127;
        float w0 = Wo[(size_t)(2*k2) * EMB + n0 + n];
        float w1 = Wo[(size_t)(2*k2 + 1) * EMB + n0 + n];
        split2(w0, w1, Bs_hi[k2*OBLD2 + n], Bs_lo[k2*OBLD2 + n]);
    }
    __syncthreads();

    float c[2][8][4];
#pragma unroll
    for (int mt = 0; mt < 2; mt++)
#pragma unroll
        for (int nt = 0; nt < 8; nt++)
#pragma unroll
            for (int j = 0; j < 4; j++) c[mt][nt][j] = 0.f;

#pragma unroll
    for (int kt = 0; kt < 4; kt++) {
        uint32_t ah[2][4], al[2][4];
#pragma unroll
        for (int mt = 0; mt < 2; mt++) {
            ldsm4(ah[mt], a_hi_base + (mt*16*OALD2 + kt*8)*4);
            ldsm4(al[mt], a_lo_base + (mt*16*OALD2 + kt*8)*4);
        }
#pragma unroll
        for (int nt = 0; nt < 8; nt++) {
            int nn = wn * 64 + nt * 8 + g;
            uint32_t bh[2], bl[2];
            bh[0] = Bs_hi[(kt*8+tg)*OBLD2 + nn];   bh[1] = Bs_hi[(kt*8+tg+4)*OBLD2 + nn];
            bl[0] = Bs_lo[(kt*8+tg)*OBLD2 + nn];   bl[1] = Bs_lo[(kt*8+tg+4)*OBLD2 + nn];
            mma16(c[0][nt], ah[0], bh);
            mma16(c[0][nt], ah[0], bl);
            mma16(c[0][nt], al[0], bh);
            mma16(c[1][nt], ah[1], bh);
            mma16(c[1][nt], ah[1], bl);
            mma16(c[1][nt], al[1], bh);
        }
    }

#pragma unroll
    for (int mt = 0; mt < 2; mt++) {
#pragma unroll
        for (int nt = 0; nt < 8; nt++) {
            int row = m0 + wm * 32 + mt * 16 + g;
            int col = n0 + wn * 64 + nt * 8 + 2 * tg;
            *(float2*)&out[(size_t)row * EMB + col]       = make_float2(c[mt][nt][0], c[mt][nt][1]);
            *(float2*)&out[(size_t)(row + 8) * EMB + col] = make_float2(c[mt][nt][2], c[mt][nt][3]);
        }
    }
}

// ---------------------------------------------------------------------------
extern "C" void kernel_launch(void* const* d_in, const int* in_sizes, int n_in,
                              void* d_out, int out_size) {
    const float* q  = (const float*)d_in[0];
    const float* kv = (const float*)d_in[1];
    const float* Wq = (const float*)d_in[2];
    const float* Wk = (const float*)d_in[3];
    const float* Wv = (const float*)d_in[4];
    const float* Wo = (const float*)d_in[5];
    float* out = (float*)d_out;

    const int proj_smem  = PROJ_SMEM_WORDS * 4;             // 113664
    const int flash_smem = FLASH_SMEM_WORDS * 4;            // 110592
    const int out_smem   = (2*128*OALD2 + 2*32*OBLD2) * 4;  // 71680
    cudaFuncSetAttribute(proj_kernel,  cudaFuncAttributeMaxDynamicSharedMemorySize, proj_smem);
    cudaFuncSetAttribute(flash_kernel, cudaFuncAttributeMaxDynamicSharedMemorySize, flash_smem);
    cudaFuncSetAttribute(out_kernel,   cudaFuncAttributeMaxDynamicSharedMemorySize, out_smem);

    prep_kernel<<<1792, 256>>>(Wq, Wk, Wv);
    proj_kernel<<<dim3(6, MROWS / 128), 256, proj_smem>>>(q, kv);
    flash_kernel<<<dim3(SEQ / 128, BATCH * KVH), 128, flash_smem>>>();
    out_kernel<<<dim3(EMB / 128, MROWS / 128), 256, out_smem>>>(Wo, out);
}